// round 12
// baseline (speedup 1.0000x reference)
#include <cuda_runtime.h>
#include <cuda_bf16.h>
#include <cstdint>
#include <math.h>

typedef unsigned long long ull;

// ============================================================
// Problem constants (fixed by the reference)
//   x:   (4096, 2048) f32      W1: (2048, 512)   b1: (512)
//   W2:  (512, 128)            b2: (128)
//   asz: (4, 12, 3)            out: (4096) f32
//
// out = measure( U_fixed @ init(com), x ); U_fixed batch-independent
// => circuit = GEMM over 256 init columns, measurement fused into
//    the GEMM epilogue (pairs adjacent by column permutation).
// ============================================================

__device__ float g_H[4096 * 512];        // relu(x@W1+b1)
__device__ float g_comp[4][4096 * 128];  // com partials (split-K=4; z=0 has bias)
__device__ __nv_bfloat16 g_xh[4096 * 2048];   // x split-hi
__device__ __nv_bfloat16 g_xl[4096 * 2048];   // x split-lo
__device__ __nv_bfloat16 g_wh[512 * 2048];    // W1^T split-hi
__device__ __nv_bfloat16 g_wl[512 * 2048];    // W1^T split-lo
__device__ __nv_bfloat16 g_utmp[4][256 * 4096]; // U staging [c][p]
__device__ __nv_bfloat16 g_u[4][4096 * 256];    // U k-contig [p][c]
__device__ __nv_bfloat16 g_ah[4096 * 256];      // amp split-hi [b][k]
__device__ __nv_bfloat16 g_al[4096 * 256];      // amp split-lo
__device__ float g_part[32][4096];              // per-N-tile measurement partials

// ------------------------------------------------------------
// helpers
// ------------------------------------------------------------
__device__ __forceinline__ uint32_t smem_u32(const void* p) {
    uint32_t a;
    asm("{ .reg .u64 t; cvta.to.shared.u64 t, %1; cvt.u32.u64 %0, t; }"
        : "=r"(a) : "l"(p));
    return a;
}
__device__ __forceinline__ void cp_async16(uint32_t saddr, const void* g) {
    asm volatile("cp.async.cg.shared.global [%0], [%1], 16;"
                 :: "r"(saddr), "l"(g) : "memory");
}
#define CP_COMMIT() asm volatile("cp.async.commit_group;" ::: "memory")
#define CP_WAIT(n)  asm volatile("cp.async.wait_group %0;" :: "n"(n) : "memory")

__device__ __forceinline__ void ldm_x4(uint32_t* r, uint32_t addr) {
    asm volatile("ldmatrix.sync.aligned.m8n8.x4.shared.b16 {%0,%1,%2,%3}, [%4];"
                 : "=r"(r[0]), "=r"(r[1]), "=r"(r[2]), "=r"(r[3]) : "r"(addr));
}
__device__ __forceinline__ void ldm_x2(uint32_t* r, uint32_t addr) {
    asm volatile("ldmatrix.sync.aligned.m8n8.x2.shared.b16 {%0,%1}, [%2];"
                 : "=r"(r[0]), "=r"(r[1]) : "r"(addr));
}
__device__ __forceinline__ void mma_bf16(float* c, const uint32_t* a,
                                         const uint32_t* b) {
    asm volatile(
        "mma.sync.aligned.m16n8k16.row.col.f32.bf16.bf16.f32 "
        "{%0,%1,%2,%3}, {%4,%5,%6,%7}, {%8,%9}, {%0,%1,%2,%3};"
        : "+f"(c[0]), "+f"(c[1]), "+f"(c[2]), "+f"(c[3])
        : "r"(a[0]), "r"(a[1]), "r"(a[2]), "r"(a[3]), "r"(b[0]), "r"(b[1]));
}
__device__ __forceinline__ uint32_t swz(uint32_t byte) {   // SW128
    return byte ^ ((byte >> 3) & 0x70u);
}
__device__ __forceinline__ ull f2mul(ull a, ull b) {
    ull d; asm("mul.rn.f32x2 %0, %1, %2;" : "=l"(d) : "l"(a), "l"(b)); return d;
}
__device__ __forceinline__ ull f2fma(ull a, ull b, ull c) {
    ull d; asm("fma.rn.f32x2 %0, %1, %2, %3;" : "=l"(d) : "l"(a), "l"(b), "l"(c)); return d;
}
__device__ __forceinline__ ull pack2(float lo, float hi) {
    ull r; asm("mov.b64 %0, {%1, %2};" : "=l"(r) : "f"(lo), "f"(hi)); return r;
}
__device__ __forceinline__ float2 unpack2(ull v) {
    float2 r; asm("mov.b64 {%0, %1}, %2;" : "=f"(r.x), "=f"(r.y) : "l"(v)); return r;
}
__device__ __forceinline__ ull uswap(ull v) {
    float2 r = unpack2(v);
    return pack2(r.y, r.x);
}

// ------------------------------------------------------------
// Pre-kernels: float split into bf16 hi/lo
// ------------------------------------------------------------
__global__ void __launch_bounds__(256)
convert_x_kernel(const float* __restrict__ x)
{
    size_t i = (size_t)blockIdx.x * 256 + threadIdx.x;   // per float4
    float4 v = reinterpret_cast<const float4*>(x)[i];
    __nv_bfloat16 h0 = __float2bfloat16_rn(v.x);
    __nv_bfloat16 h1 = __float2bfloat16_rn(v.y);
    __nv_bfloat16 h2 = __float2bfloat16_rn(v.z);
    __nv_bfloat16 h3 = __float2bfloat16_rn(v.w);
    __nv_bfloat16 l0 = __float2bfloat16_rn(v.x - __bfloat162float(h0));
    __nv_bfloat16 l1 = __float2bfloat16_rn(v.y - __bfloat162float(h1));
    __nv_bfloat16 l2 = __float2bfloat16_rn(v.z - __bfloat162float(h2));
    __nv_bfloat16 l3 = __float2bfloat16_rn(v.w - __bfloat162float(h3));
    reinterpret_cast<__nv_bfloat162*>(g_xh)[i*2]   = __nv_bfloat162(h0, h1);
    reinterpret_cast<__nv_bfloat162*>(g_xh)[i*2+1] = __nv_bfloat162(h2, h3);
    reinterpret_cast<__nv_bfloat162*>(g_xl)[i*2]   = __nv_bfloat162(l0, l1);
    reinterpret_cast<__nv_bfloat162*>(g_xl)[i*2+1] = __nv_bfloat162(l2, l3);
}

__global__ void __launch_bounds__(256)
transpose_w1_kernel(const float* __restrict__ W1)
{
    __shared__ float tile[32][33];
    int n0 = blockIdx.x * 32;
    int k0 = blockIdx.y * 32;
    int tx = threadIdx.x % 32, ty = threadIdx.x / 32;
#pragma unroll
    for (int j = 0; j < 4; ++j)
        tile[ty + 8*j][tx] = W1[(size_t)(k0 + ty + 8*j) * 512 + n0 + tx];
    __syncthreads();
#pragma unroll
    for (int j = 0; j < 4; ++j) {
        float v = tile[tx][ty + 8*j];
        __nv_bfloat16 h = __float2bfloat16_rn(v);
        __nv_bfloat16 l = __float2bfloat16_rn(v - __bfloat162float(h));
        size_t o = (size_t)(n0 + ty + 8*j) * 2048 + k0 + tx;
        g_wh[o] = h;
        g_wl[o] = l;
    }
}

// ------------------------------------------------------------
// gemm1 via mma.sync bf16 split-3 (proven since R5)
// ------------------------------------------------------------
__global__ void __launch_bounds__(256)
gemm1_mma_kernel(const float* __restrict__ b1)
{
    extern __shared__ __align__(128) char smem[];
    const uint32_t sb = smem_u32(smem);
    const int tid  = threadIdx.x;
    const int wid  = tid >> 5;
    const int lane = tid & 31;
    const int wm = wid & 1, wn = wid >> 1;
    const int bm = blockIdx.y * 128, bn = blockIdx.x * 128;

    float acc[4][4][4];
#pragma unroll
    for (int mt = 0; mt < 4; ++mt)
#pragma unroll
        for (int nt = 0; nt < 4; ++nt)
#pragma unroll
            for (int j = 0; j < 4; ++j) acc[mt][nt][j] = 0.f;

    const __nv_bfloat16* srcs[4] = { g_xh, g_xl, g_wh, g_wl };

    {
#pragma unroll
        for (int t = 0; t < 4; ++t) {
            int row0 = (t < 2) ? bm : bn;
            uint32_t base = sb + t * 16384u;
#pragma unroll
            for (int it = 0; it < 4; ++it) {
                int id = tid + it * 256;
                int r = id >> 3, blk = id & 7;
                cp_async16(base + swz((uint32_t)(r * 128 + blk * 16)),
                           srcs[t] + (size_t)(row0 + r) * 2048 + blk * 8);
            }
        }
        CP_COMMIT();
    }

#pragma unroll 1
    for (int c = 0; c < 32; ++c) {
        if (c + 1 < 32) {
            const int kt = (c + 1) * 64;
            const uint32_t bufo = (uint32_t)((c + 1) & 1) * 65536u;
#pragma unroll
            for (int t = 0; t < 4; ++t) {
                int row0 = (t < 2) ? bm : bn;
                uint32_t base = sb + bufo + t * 16384u;
#pragma unroll
                for (int it = 0; it < 4; ++it) {
                    int id = tid + it * 256;
                    int r = id >> 3, blk = id & 7;
                    cp_async16(base + swz((uint32_t)(r * 128 + blk * 16)),
                               srcs[t] + (size_t)(row0 + r) * 2048 + kt + blk * 8);
                }
            }
            CP_COMMIT();
            CP_WAIT(1);
        } else {
            CP_WAIT(0);
        }
        __syncthreads();

        const uint32_t base = sb + (uint32_t)(c & 1) * 65536u;
#pragma unroll
        for (int kk = 0; kk < 4; ++kk) {
            uint32_t ah[4][4], al[4][4], bh[4][2], bl[4][2];
#pragma unroll
            for (int mt = 0; mt < 4; ++mt) {
                uint32_t byte = (uint32_t)((wm * 64 + mt * 16 + (lane & 15)) * 128
                                           + (kk * 2 + (lane >> 4)) * 16);
                uint32_t ad = base + swz(byte);
                ldm_x4(ah[mt], ad);
                ldm_x4(al[mt], ad + 16384u);
            }
#pragma unroll
            for (int nt = 0; nt < 4; ++nt) {
                uint32_t byte = (uint32_t)((wn * 32 + nt * 8 + (lane & 7)) * 128
                                           + (kk * 2 + ((lane >> 3) & 1)) * 16);
                uint32_t bd = base + 32768u + swz(byte);
                ldm_x2(bh[nt], bd);
                ldm_x2(bl[nt], bd + 16384u);
            }
#pragma unroll
            for (int mt = 0; mt < 4; ++mt)
#pragma unroll
                for (int nt = 0; nt < 4; ++nt) {
                    mma_bf16(acc[mt][nt], ah[mt], bh[nt]);
                    mma_bf16(acc[mt][nt], ah[mt], bl[nt]);
                    mma_bf16(acc[mt][nt], al[mt], bh[nt]);
                }
        }
        __syncthreads();
    }

#pragma unroll
    for (int mt = 0; mt < 4; ++mt) {
        int row = bm + wm * 64 + mt * 16 + (lane >> 2);
#pragma unroll
        for (int nt = 0; nt < 4; ++nt) {
            int col = bn + wn * 32 + nt * 8 + (lane & 3) * 2;
            float b0 = b1[col], bq = b1[col + 1];
            float2 v0 = make_float2(fmaxf(acc[mt][nt][0] + b0, 0.f),
                                    fmaxf(acc[mt][nt][1] + bq, 0.f));
            float2 v1 = make_float2(fmaxf(acc[mt][nt][2] + b0, 0.f),
                                    fmaxf(acc[mt][nt][3] + bq, 0.f));
            *reinterpret_cast<float2*>(&g_H[(size_t)row * 512 + col])       = v0;
            *reinterpret_cast<float2*>(&g_H[(size_t)(row + 8) * 512 + col]) = v1;
        }
    }
}

// ------------------------------------------------------------
// fp32 SGEMM for gemm2 — 32x64 tiles, split-K=4 => 1024 CTAs
// ------------------------------------------------------------
template<int BM, int BN, int BK, int TM, int TN>
__device__ __forceinline__ void sgemm_body(
    const float* __restrict__ A, const float* __restrict__ Bm,
    const float* __restrict__ bias, float* __restrict__ C,
    int N, int K, int lda)
{
    __shared__ float As[BK][BM];
    __shared__ float Bs[BK][BN];
    const int tid = threadIdx.x;
    const int NX = BN / TN;
    const int tx = tid % NX;
    const int ty = tid / NX;
    const int bm = blockIdx.y * BM;
    const int bn = blockIdx.x * BN;

    ull acc[TM / 2][TN];
#pragma unroll
    for (int i = 0; i < TM / 2; ++i)
#pragma unroll
        for (int j = 0; j < TN; ++j) acc[i][j] = 0ull;

    for (int kt = 0; kt < K; kt += BK) {
#pragma unroll
        for (int l = 0; l < (BM * BK) / (256 * 4); ++l) {
            int id  = tid + l * 256;
            int row = id / (BK / 4);
            int c   = id % (BK / 4);
            float4 v = *reinterpret_cast<const float4*>(
                A + (size_t)(bm + row) * lda + kt + c * 4);
            As[c*4+0][row] = v.x; As[c*4+1][row] = v.y;
            As[c*4+2][row] = v.z; As[c*4+3][row] = v.w;
        }
#pragma unroll
        for (int l = 0; l < (BK * BN) / (256 * 4); ++l) {
            int id = tid + l * 256;
            int kr = id / (BN / 4);
            int c  = id % (BN / 4);
            *reinterpret_cast<float4*>(&Bs[kr][c*4]) =
                *reinterpret_cast<const float4*>(
                    Bm + (size_t)(kt + kr) * N + bn + c * 4);
        }
        __syncthreads();
#pragma unroll
        for (int k = 0; k < BK; ++k) {
            ull ra[TM / 2];
            float rb[TN];
#pragma unroll
            for (int i = 0; i < TM / 2; ++i)
                ra[i] = *reinterpret_cast<const ull*>(&As[k][ty*TM + 2*i]);
#pragma unroll
            for (int j = 0; j < TN; j += 4)
                *reinterpret_cast<float4*>(&rb[j]) =
                    *reinterpret_cast<const float4*>(&Bs[k][tx*TN + j]);
#pragma unroll
            for (int j = 0; j < TN; ++j) {
                ull rbb = pack2(rb[j], rb[j]);
#pragma unroll
                for (int i = 0; i < TM / 2; ++i)
                    acc[i][j] = f2fma(ra[i], rbb, acc[i][j]);
            }
        }
        __syncthreads();
    }
#pragma unroll
    for (int i = 0; i < TM / 2; ++i) {
        int row = bm + ty * TM + 2 * i;
#pragma unroll
        for (int j = 0; j < TN; ++j) {
            int col = bn + tx * TN + j;
            float bv = bias ? bias[col] : 0.f;
            float2 u = unpack2(acc[i][j]);
            C[(size_t)row * N + col]       = u.x + bv;
            C[(size_t)(row + 1) * N + col] = u.y + bv;
        }
    }
}

__global__ void __launch_bounds__(256)
gemm2_kernel(const float* __restrict__ W2, const float* __restrict__ b2)
{
    const int z = blockIdx.z;
    const float* A  = g_H + z * 128;
    const float* Bm = W2 + (size_t)(z * 128) * 128;
    float* C = g_comp[z];
    sgemm_body<32, 64, 32, 2, 4>(A, Bm, z ? nullptr : b2, C, 128, 128, 512);
}

// ------------------------------------------------------------
// amp kernel: A[b, 2j|2j+1] = cos/sin(com_j/2) * 2^-3.5, bf16 split
// ------------------------------------------------------------
__global__ void __launch_bounds__(256)
amp_kernel()
{
    int id = blockIdx.x * 256 + threadIdx.x;
    int b = id >> 7, j = id & 127;
    const float inv = 0.08838834764831844f;    // 2^-3.5
    float a = 0.5f * (g_comp[0][b * 128 + j] + g_comp[1][b * 128 + j]
                    + g_comp[2][b * 128 + j] + g_comp[3][b * 128 + j]);
    float sa, ca; sincosf(a, &sa, &ca);
    float vc = ca * inv, vs = sa * inv;
    __nv_bfloat16 ch = __float2bfloat16_rn(vc);
    __nv_bfloat16 cl = __float2bfloat16_rn(vc - __bfloat162float(ch));
    __nv_bfloat16 sh = __float2bfloat16_rn(vs);
    __nv_bfloat16 sl = __float2bfloat16_rn(vs - __bfloat162float(sh));
    size_t o = (size_t)b * 256 + 2 * j;
    g_ah[o] = ch; g_ah[o + 1] = sh;
    g_al[o] = cl; g_al[o + 1] = sl;
}

// ------------------------------------------------------------
// U-build (proven at R9): evolve 256 basis columns, emit bf16
// hi/lo of re/im at permuted position (pairs adjacent).
// ------------------------------------------------------------
struct GroupMeta {
    unsigned cmk[4];
    unsigned rmk[4];
    unsigned d[8];
    int      gidx[4];
};
struct CircMeta {
    GroupMeta grp[12];
    unsigned lfmask[11];
    unsigned cz;
    unsigned minv[12];
};

__global__ void __launch_bounds__(256, 3)
ubuild_kernel(const float* __restrict__ asz, CircMeta meta)
{
    __shared__ float2 st[4096];
    __shared__ ull    mats[48][8];
    const int c   = blockIdx.x;
    const int tid = threadIdx.x;
    ull* stq = reinterpret_cast<ull*>(st);

    if (tid < 48) {
        float phi = asz[tid*3+0], th = asz[tid*3+1], om = asz[tid*3+2];
        float cc, s, cp, sp, cm, sm;
        sincosf(0.5f * th, &s, &cc);
        sincosf(0.5f * (phi + om), &sp, &cp);
        sincosf(0.5f * (phi - om), &sm, &cm);
        float2 m00 = make_float2( cp * cc, -sp * cc);
        float2 m01 = make_float2(-cm * s,  -sm * s);
        float2 m10 = make_float2( cm * s,  -sm * s);
        float2 m11 = make_float2( cp * cc,  sp * cc);
        mats[tid][0] = pack2(m00.x, m00.x); mats[tid][1] = pack2(-m00.y, m00.y);
        mats[tid][2] = pack2(m01.x, m01.x); mats[tid][3] = pack2(-m01.y, m01.y);
        mats[tid][4] = pack2(m10.x, m10.x); mats[tid][5] = pack2(-m10.y, m10.y);
        mats[tid][6] = pack2(m11.x, m11.x); mats[tid][7] = pack2(-m11.y, m11.y);
    }
#pragma unroll
    for (int i = 0; i < 16; ++i) st[tid + i * 256] = make_float2(0.f, 0.f);
    __syncthreads();

    if (tid == 0) {
        int j = c >> 1, t = c & 1;
        int rj = (int)(__brev((unsigned)j) >> 25);  // rev7
        int n0 = (t ? 2048 : 0) + rj * 16;
        st[n0] = make_float2(1.f, 0.f);
    }
    __syncthreads();

#pragma unroll 1
    for (int G = 0; G < 12; ++G) {
        const GroupMeta& gm = meta.grp[G];
        unsigned rep = 0;
#pragma unroll
        for (int j = 0; j < 8; ++j)
            rep ^= ((tid >> j) & 1u) ? gm.d[j] : 0u;

        unsigned idx[16];
#pragma unroll
        for (int bb = 0; bb < 16; ++bb) {
            unsigned o = rep;
            if (bb & 1) o ^= gm.cmk[0];
            if (bb & 2) o ^= gm.cmk[1];
            if (bb & 4) o ^= gm.cmk[2];
            if (bb & 8) o ^= gm.cmk[3];
            idx[bb] = o;
        }
        ull v[16];
#pragma unroll
        for (int bb = 0; bb < 16; ++bb) v[bb] = stq[idx[bb]];

#pragma unroll
        for (int gg = 0; gg < 4; ++gg) {
            const ull* mp = mats[gm.gidx[gg]];
            bool lb = (__popc(gm.rmk[gg] & rep) & 1) != 0;
            ull a0r = lb ? mp[6] : mp[0], a0i = lb ? mp[7] : mp[1];
            ull a1r = lb ? mp[4] : mp[2], a1i = lb ? mp[5] : mp[3];
            ull b0r = lb ? mp[2] : mp[4], b0i = lb ? mp[3] : mp[5];
            ull b1r = lb ? mp[0] : mp[6], b1i = lb ? mp[1] : mp[7];
            const unsigned bit = 1u << gg;
#pragma unroll
            for (int bb = 0; bb < 16; ++bb) {
                if (bb & bit) continue;
                ull s0 = v[bb], s1 = v[bb ^ bit];
                ull s0s = uswap(s0), s1s = uswap(s1);
                ull n0 = f2mul(a0r, s0);
                n0 = f2fma(a0i, s0s, n0);
                n0 = f2fma(a1r, s1, n0);
                n0 = f2fma(a1i, s1s, n0);
                ull n1 = f2mul(b0r, s0);
                n1 = f2fma(b0i, s0s, n1);
                n1 = f2fma(b1r, s1, n1);
                n1 = f2fma(b1i, s1s, n1);
                v[bb] = n0; v[bb ^ bit] = n1;
            }
        }
#pragma unroll
        for (int bb = 0; bb < 16; ++bb) stq[idx[bb]] = v[bb];
        __syncthreads();
    }

#pragma unroll
    for (int i = 0; i < 16; ++i) {
        unsigned n = tid + i * 256;
        unsigned iw = 0;
#pragma unroll
        for (int q = 0; q < 12; ++q)
            iw |= (unsigned)(__popc(meta.minv[q] & n) & 1) << q;
        unsigned p = ((iw & 2047u) << 1) | (iw >> 11);
        float2 s = st[n];
        __nv_bfloat16 rh = __float2bfloat16_rn(s.x);
        __nv_bfloat16 rl = __float2bfloat16_rn(s.x - __bfloat162float(rh));
        __nv_bfloat16 ih = __float2bfloat16_rn(s.y);
        __nv_bfloat16 il = __float2bfloat16_rn(s.y - __bfloat162float(ih));
        size_t o = (size_t)c * 4096 + p;
        g_utmp[0][o] = rh; g_utmp[1][o] = rl;
        g_utmp[2][o] = ih; g_utmp[3][o] = il;
    }
}

// transpose U staging [c][p] -> k-contig [p][c]
__global__ void __launch_bounds__(256)
transpose_u_kernel()
{
    __shared__ __nv_bfloat16 t[32][33];
    const int z  = blockIdx.z;
    const int p0 = blockIdx.x * 32;
    const int c0 = blockIdx.y * 32;
    int tx = threadIdx.x % 32, ty = threadIdx.x / 32;
#pragma unroll
    for (int j = 0; j < 4; ++j)
        t[ty + 8*j][tx] = g_utmp[z][(size_t)(c0 + ty + 8*j) * 4096 + p0 + tx];
    __syncthreads();
#pragma unroll
    for (int j = 0; j < 4; ++j)
        g_u[z][(size_t)(p0 + ty + 8*j) * 256 + c0 + tx] = t[tx][ty + 8*j];
}

// ------------------------------------------------------------
// Fused state GEMM + measurement. R12: SINGLE-buffered smem
// (81920 B dynamic) => 2 CTAs/SM; cross-CTA overlap replaces the
// intra-CTA double buffer. x tile staged in smem (R11 fix kept).
// CTA tile 64(M=batch) x 128(N=state pairs), K=256.
// smem: Ah@0, Al@8192, B z@16384+z*16384
// ------------------------------------------------------------
__global__ void __launch_bounds__(256)
state_fused_kernel(const float* __restrict__ x)
{
    extern __shared__ __align__(128) char smem[];
    __shared__ float psum[64][4];
    __shared__ float xs[64][68];          // stride 68: conflict-free epilogue
    const uint32_t sb = smem_u32(smem);
    const int tid = threadIdx.x;
    const int wid = tid >> 5, lane = tid & 31;
    const int wm = wid & 1, wn = wid >> 1;
    const int bm = blockIdx.y * 64;
    const int bx = blockIdx.x;            // N tile (128 cols = 64 pairs)
    const int bn = bx * 128;

    float accre[2][4][4], accim[2][4][4];
#pragma unroll
    for (int mt = 0; mt < 2; ++mt)
#pragma unroll
        for (int nt = 0; nt < 4; ++nt)
#pragma unroll
            for (int j = 0; j < 4; ++j) { accre[mt][nt][j] = 0.f; accim[mt][nt][j] = 0.f; }

    const __nv_bfloat16* bsrc[4] = { g_u[0], g_u[1], g_u[2], g_u[3] };

    // stage x tile [64 rows][64 cols] coalesced
#pragma unroll
    for (int it = 0; it < 4; ++it) {
        int id = tid + it * 256;          // 1024 float4 loads = 64 x 16
        int r = id >> 4, c4 = id & 15;
        float4 v = *reinterpret_cast<const float4*>(
            &x[(size_t)(bm + r) * 2048 + bx * 64 + c4 * 4]);
        xs[r][c4 * 4 + 0] = v.x;
        xs[r][c4 * 4 + 1] = v.y;
        xs[r][c4 * 4 + 2] = v.z;
        xs[r][c4 * 4 + 3] = v.w;
    }

#pragma unroll 1
    for (int c = 0; c < 4; ++c) {
        const int kt = c * 64;
#pragma unroll
        for (int s = 0; s < 2; ++s) {
            const __nv_bfloat16* g = s ? g_al : g_ah;
#pragma unroll
            for (int it = 0; it < 2; ++it) {
                int id = tid + it * 256;
                int r = id >> 3, blk = id & 7;
                cp_async16(sb + (uint32_t)(s * 8192) + swz((uint32_t)(r * 128 + blk * 16)),
                           g + (size_t)(bm + r) * 256 + kt + blk * 8);
            }
        }
#pragma unroll
        for (int z = 0; z < 4; ++z) {
#pragma unroll
            for (int it = 0; it < 4; ++it) {
                int id = tid + it * 256;
                int r = id >> 3, blk = id & 7;
                cp_async16(sb + 16384u + (uint32_t)(z * 16384) + swz((uint32_t)(r * 128 + blk * 16)),
                           bsrc[z] + (size_t)(bn + r) * 256 + kt + blk * 8);
            }
        }
        CP_COMMIT();
        CP_WAIT(0);
        __syncthreads();

        const uint32_t base = sb;
#pragma unroll
        for (int kk = 0; kk < 4; ++kk) {
            uint32_t ah[2][4], al[2][4];
#pragma unroll
            for (int mt = 0; mt < 2; ++mt) {
                uint32_t byte = (uint32_t)((wm * 32 + mt * 16 + (lane & 15)) * 128
                                           + (kk * 2 + (lane >> 4)) * 16);
                uint32_t ad = base + swz(byte);
                ldm_x4(ah[mt], ad);
                ldm_x4(al[mt], ad + 8192u);
            }
#pragma unroll
            for (int nt = 0; nt < 4; ++nt) {
                uint32_t byte = (uint32_t)((wn * 32 + nt * 8 + (lane & 7)) * 128
                                           + (kk * 2 + ((lane >> 3) & 1)) * 16);
                uint32_t sw = swz(byte);
                uint32_t brh[2], brl[2], bih[2], bil[2];
                ldm_x2(brh, base + 16384u + sw);
                ldm_x2(brl, base + 32768u + sw);
                ldm_x2(bih, base + 49152u + sw);
                ldm_x2(bil, base + 65536u + sw);
#pragma unroll
                for (int mt = 0; mt < 2; ++mt) {
                    mma_bf16(accre[mt][nt], ah[mt], brh);
                    mma_bf16(accre[mt][nt], ah[mt], brl);
                    mma_bf16(accre[mt][nt], al[mt], brh);
                    mma_bf16(accim[mt][nt], ah[mt], bih);
                    mma_bf16(accim[mt][nt], ah[mt], bil);
                    mma_bf16(accim[mt][nt], al[mt], bih);
                }
            }
        }
        __syncthreads();   // buffer reuse barrier
    }

    // fused measurement epilogue: x from smem (conflict-free)
    float rowacc[2][2];
    rowacc[0][0] = rowacc[0][1] = rowacc[1][0] = rowacc[1][1] = 0.f;
#pragma unroll
    for (int mt = 0; mt < 2; ++mt) {
#pragma unroll
        for (int nt = 0; nt < 4; ++nt) {
            int lj = wn * 16 + nt * 4 + (lane & 3);
            int lr0 = wm * 32 + mt * 16 + (lane >> 2);
#pragma unroll
            for (int off = 0; off < 2; ++off) {
                float s0r = accre[mt][nt][off * 2];
                float s1r = accre[mt][nt][off * 2 + 1];
                float s0i = accim[mt][nt][off * 2];
                float s1i = accim[mt][nt][off * 2 + 1];
                float xv = xs[lr0 + off * 8][lj];
                float sv, cv;
                sincosf(xv, &sv, &cv);
                rowacc[mt][off] += cv * ((s1r*s1r + s1i*s1i) - (s0r*s0r + s0i*s0i))
                                 - 2.f * sv * (s0r*s1r + s0i*s1i);
            }
        }
    }
#pragma unroll
    for (int mt = 0; mt < 2; ++mt)
#pragma unroll
        for (int off = 0; off < 2; ++off) {
            float r = rowacc[mt][off];
            r += __shfl_down_sync(0xffffffffu, r, 2);
            r += __shfl_down_sync(0xffffffffu, r, 1);
            if ((lane & 3) == 0)
                psum[wm * 32 + mt * 16 + (lane >> 2) + off * 8][wn] = r;
        }
    __syncthreads();
    if (tid < 64)
        g_part[bx][bm + tid] =
            psum[tid][0] + psum[tid][1] + psum[tid][2] + psum[tid][3];
}

__global__ void __launch_bounds__(256)
finalsum_kernel(float* __restrict__ out)
{
    int b = blockIdx.x * 256 + threadIdx.x;
    float s = 0.f;
#pragma unroll
    for (int z = 0; z < 32; ++z) s += g_part[z][b];
    out[b] = s;
}

// ------------------------------------------------------------
// Host: GF(2) bookkeeping (proven) + minv
// ------------------------------------------------------------
struct Ech {
    unsigned e[12];
    Ech() { for (int i = 0; i < 12; ++i) e[i] = 0; }
    unsigned reduce(unsigned v) const {
        for (int b = 11; b >= 0; --b)
            if (((v >> b) & 1u) && e[b]) v ^= e[b];
        return v;
    }
    bool insert(unsigned v) {
        v = reduce(v);
        if (!v) return false;
        int b = 11;
        while (!((v >> b) & 1u)) --b;
        e[b] = v;
        return true;
    }
};

static unsigned gf2_cnot_rev(unsigned v, int r) {
    for (int w = 11; w >= 0; --w) {
        int t = (w + r) % 12;
        if ((v >> (11 - w)) & 1u) v ^= 1u << (11 - t);
    }
    return v;
}

static void gf2_invert(const unsigned colv[12], unsigned invr[12]) {
    unsigned row[12], aug[12];
    for (int p = 0; p < 12; ++p) {
        unsigned rr = 0;
        for (int q = 0; q < 12; ++q) rr |= ((colv[q] >> p) & 1u) << q;
        row[p] = rr; aug[p] = 1u << p;
    }
    for (int i = 0; i < 12; ++i) {
        int piv = i;
        while (!((row[piv] >> i) & 1u)) ++piv;
        unsigned t = row[i]; row[i] = row[piv]; row[piv] = t;
        t = aug[i]; aug[i] = aug[piv]; aug[piv] = t;
        for (int jj = 0; jj < 12; ++jj)
            if (jj != i && ((row[jj] >> i) & 1u)) {
                row[jj] ^= row[i]; aug[jj] ^= aug[i];
            }
    }
    for (int p = 0; p < 12; ++p) invr[p] = aug[p];
}

static void build_meta(CircMeta& meta) {
    unsigned macc[12];
    for (int p = 0; p < 12; ++p) macc[p] = 1u << p;
    for (int l = 0; l < 4; ++l) {
        unsigned row[12], aug[12];
        for (int p = 0; p < 12; ++p) {
            unsigned rr = 0;
            for (int q = 0; q < 12; ++q) rr |= ((macc[q] >> p) & 1u) << q;
            row[p] = rr; aug[p] = 1u << p;
        }
        for (int i = 0; i < 12; ++i) {
            int piv = i;
            while (!((row[piv] >> i) & 1u)) ++piv;
            unsigned t = row[i]; row[i] = row[piv]; row[piv] = t;
            t = aug[i]; aug[i] = aug[piv]; aug[piv] = t;
            for (int jj = 0; jj < 12; ++jj)
                if (jj != i && ((row[jj] >> i) & 1u)) {
                    row[jj] ^= row[i]; aug[jj] ^= aug[i];
                }
        }
        for (int grp = 0; grp < 3; ++grp) {
            GroupMeta& gm = meta.grp[l * 3 + grp];
            Ech ech;
            for (int t = 0; t < 4; ++t) {
                int w = grp * 4 + t;
                gm.cmk[t]  = macc[11 - w];
                gm.rmk[t]  = aug[11 - w];
                gm.gidx[t] = l * 12 + w;
                ech.insert(gm.cmk[t]);
            }
            int nd = 0;
            unsigned proje[5] = {0, 0, 0, 0, 0};
            for (unsigned v = 1; v < 4096 && nd < 5; ++v) {
                if (ech.reduce(v) == 0) continue;
                unsigned p = v & 31u;
                for (int b = 4; b >= 0; --b)
                    if (((p >> b) & 1u) && proje[b]) p ^= proje[b];
                if (p == 0) continue;
                ech.insert(v);
                int pb = 4;
                while (!((p >> pb) & 1u)) --pb;
                proje[pb] = p;
                gm.d[nd++] = v;
            }
            for (unsigned v = 1; v < 4096 && nd < 8; ++v)
                if (ech.insert(v)) gm.d[nd++] = v;
        }
        int r = l % 11 + 1;
        unsigned nmacc[12];
        for (int p = 0; p < 12; ++p) {
            unsigned u = gf2_cnot_rev(1u << p, r);
            unsigned a = 0;
            for (int q = 0; q < 12; ++q)
                if ((u >> q) & 1u) a ^= macc[q];
            nmacc[p] = a;
        }
        for (int p = 0; p < 12; ++p) macc[p] = nmacc[p];
    }
    for (int q = 0; q < 11; ++q) meta.lfmask[q] = macc[10 - q];
    meta.cz = macc[11];

    unsigned colv[12];
    for (int q = 0; q < 11; ++q) colv[q] = meta.lfmask[q];
    colv[11] = meta.cz;
    gf2_invert(colv, meta.minv);
}

// ------------------------------------------------------------
// Side stream for the U-build chain (created once at load time,
// before any capture; fork/join via events is capture-legal).
// ------------------------------------------------------------
struct StreamPack {
    cudaStream_t s2;
    cudaEvent_t evF, evJ;
    StreamPack() {
        cudaStreamCreateWithFlags(&s2, cudaStreamNonBlocking);
        cudaEventCreateWithFlags(&evF, cudaEventDisableTiming);
        cudaEventCreateWithFlags(&evJ, cudaEventDisableTiming);
    }
};
static StreamPack g_sp;

// ------------------------------------------------------------
extern "C" void kernel_launch(void* const* d_in, const int* in_sizes, int n_in,
                              void* d_out, int out_size)
{
    const float* x   = (const float*)d_in[0];
    const float* W1  = (const float*)d_in[1];
    const float* b1  = (const float*)d_in[2];
    const float* W2  = (const float*)d_in[3];
    const float* b2  = (const float*)d_in[4];
    const float* asz = (const float*)d_in[5];
    float* out = (float*)d_out;

    CircMeta meta;
    build_meta(meta);

    cudaFuncSetAttribute(gemm1_mma_kernel,
                         cudaFuncAttributeMaxDynamicSharedMemorySize, 131072);
    cudaFuncSetAttribute(state_fused_kernel,
                         cudaFuncAttributeMaxDynamicSharedMemorySize, 81920);

    // fork: U-build chain on side stream (independent of classical path)
    cudaEventRecord(g_sp.evF, 0);
    cudaStreamWaitEvent(g_sp.s2, g_sp.evF, 0);
    ubuild_kernel<<<256, 256, 0, g_sp.s2>>>(asz, meta);
    transpose_u_kernel<<<dim3(128, 8, 4), 256, 0, g_sp.s2>>>();
    cudaEventRecord(g_sp.evJ, g_sp.s2);

    // classical path on default stream
    convert_x_kernel<<<4096 * 2048 / 4 / 256, 256>>>(x);
    transpose_w1_kernel<<<dim3(16, 64), 256>>>(W1);
    gemm1_mma_kernel<<<dim3(4, 32), 256, 131072>>>(b1);
    gemm2_kernel<<<dim3(2, 128, 4), 256>>>(W2, b2);
    amp_kernel<<<2048, 256>>>();

    // join, then fused state GEMM + measurement
    cudaStreamWaitEvent(0, g_sp.evJ, 0);
    state_fused_kernel<<<dim3(32, 64), 256, 81920>>>(x);
    finalsum_kernel<<<16, 256>>>(out);
}

// round 13
// speedup vs baseline: 1.0428x; 1.0428x over previous
#include <cuda_runtime.h>
#include <cuda_bf16.h>
#include <cstdint>
#include <math.h>

typedef unsigned long long ull;

// ============================================================
// Problem constants (fixed by the reference)
//   x:   (4096, 2048) f32      W1: (2048, 512)   b1: (512)
//   W2:  (512, 128)            b2: (128)
//   asz: (4, 12, 3)            out: (4096) f32
//
// out = measure( U_fixed @ init(com), x ); U_fixed batch-independent
// => circuit = GEMM over 256 init columns, measurement fused into
//    the GEMM epilogue (pairs adjacent by column permutation).
// ============================================================

__device__ float g_H[4096 * 512];        // relu(x@W1+b1)
__device__ float g_comp[4][4096 * 128];  // com partials (split-K=4; z=0 has bias)
__device__ __nv_bfloat16 g_xh[4096 * 2048];   // x split-hi
__device__ __nv_bfloat16 g_xl[4096 * 2048];   // x split-lo
__device__ __nv_bfloat16 g_wh[512 * 2048];    // W1^T split-hi
__device__ __nv_bfloat16 g_wl[512 * 2048];    // W1^T split-lo
__device__ __nv_bfloat16 g_utmp[4][256 * 4096]; // U staging [c][p]
__device__ __nv_bfloat16 g_u[4][4096 * 256];    // U k-contig [p][c]
__device__ __nv_bfloat16 g_ah[4096 * 256];      // amp split-hi [b][k]
__device__ __nv_bfloat16 g_al[4096 * 256];      // amp split-lo
__device__ float g_part[32][4096];              // per-N-tile measurement partials

// ------------------------------------------------------------
// helpers
// ------------------------------------------------------------
__device__ __forceinline__ uint32_t smem_u32(const void* p) {
    uint32_t a;
    asm("{ .reg .u64 t; cvta.to.shared.u64 t, %1; cvt.u32.u64 %0, t; }"
        : "=r"(a) : "l"(p));
    return a;
}
__device__ __forceinline__ void cp_async16(uint32_t saddr, const void* g) {
    asm volatile("cp.async.cg.shared.global [%0], [%1], 16;"
                 :: "r"(saddr), "l"(g) : "memory");
}
#define CP_COMMIT() asm volatile("cp.async.commit_group;" ::: "memory")
#define CP_WAIT(n)  asm volatile("cp.async.wait_group %0;" :: "n"(n) : "memory")

__device__ __forceinline__ void ldm_x4(uint32_t* r, uint32_t addr) {
    asm volatile("ldmatrix.sync.aligned.m8n8.x4.shared.b16 {%0,%1,%2,%3}, [%4];"
                 : "=r"(r[0]), "=r"(r[1]), "=r"(r[2]), "=r"(r[3]) : "r"(addr));
}
__device__ __forceinline__ void ldm_x2(uint32_t* r, uint32_t addr) {
    asm volatile("ldmatrix.sync.aligned.m8n8.x2.shared.b16 {%0,%1}, [%2];"
                 : "=r"(r[0]), "=r"(r[1]) : "r"(addr));
}
__device__ __forceinline__ void mma_bf16(float* c, const uint32_t* a,
                                         const uint32_t* b) {
    asm volatile(
        "mma.sync.aligned.m16n8k16.row.col.f32.bf16.bf16.f32 "
        "{%0,%1,%2,%3}, {%4,%5,%6,%7}, {%8,%9}, {%0,%1,%2,%3};"
        : "+f"(c[0]), "+f"(c[1]), "+f"(c[2]), "+f"(c[3])
        : "r"(a[0]), "r"(a[1]), "r"(a[2]), "r"(a[3]), "r"(b[0]), "r"(b[1]));
}
__device__ __forceinline__ uint32_t swz(uint32_t byte) {   // SW128
    return byte ^ ((byte >> 3) & 0x70u);
}
__device__ __forceinline__ ull f2mul(ull a, ull b) {
    ull d; asm("mul.rn.f32x2 %0, %1, %2;" : "=l"(d) : "l"(a), "l"(b)); return d;
}
__device__ __forceinline__ ull f2fma(ull a, ull b, ull c) {
    ull d; asm("fma.rn.f32x2 %0, %1, %2, %3;" : "=l"(d) : "l"(a), "l"(b), "l"(c)); return d;
}
__device__ __forceinline__ ull pack2(float lo, float hi) {
    ull r; asm("mov.b64 %0, {%1, %2};" : "=l"(r) : "f"(lo), "f"(hi)); return r;
}
__device__ __forceinline__ float2 unpack2(ull v) {
    float2 r; asm("mov.b64 {%0, %1}, %2;" : "=f"(r.x), "=f"(r.y) : "l"(v)); return r;
}
__device__ __forceinline__ ull uswap(ull v) {
    float2 r = unpack2(v);
    return pack2(r.y, r.x);
}

// ------------------------------------------------------------
// Pre-kernels: float split into bf16 hi/lo
// ------------------------------------------------------------
__global__ void __launch_bounds__(256)
convert_x_kernel(const float* __restrict__ x)
{
    size_t i = (size_t)blockIdx.x * 256 + threadIdx.x;   // per float4
    float4 v = reinterpret_cast<const float4*>(x)[i];
    __nv_bfloat16 h0 = __float2bfloat16_rn(v.x);
    __nv_bfloat16 h1 = __float2bfloat16_rn(v.y);
    __nv_bfloat16 h2 = __float2bfloat16_rn(v.z);
    __nv_bfloat16 h3 = __float2bfloat16_rn(v.w);
    __nv_bfloat16 l0 = __float2bfloat16_rn(v.x - __bfloat162float(h0));
    __nv_bfloat16 l1 = __float2bfloat16_rn(v.y - __bfloat162float(h1));
    __nv_bfloat16 l2 = __float2bfloat16_rn(v.z - __bfloat162float(h2));
    __nv_bfloat16 l3 = __float2bfloat16_rn(v.w - __bfloat162float(h3));
    reinterpret_cast<__nv_bfloat162*>(g_xh)[i*2]   = __nv_bfloat162(h0, h1);
    reinterpret_cast<__nv_bfloat162*>(g_xh)[i*2+1] = __nv_bfloat162(h2, h3);
    reinterpret_cast<__nv_bfloat162*>(g_xl)[i*2]   = __nv_bfloat162(l0, l1);
    reinterpret_cast<__nv_bfloat162*>(g_xl)[i*2+1] = __nv_bfloat162(l2, l3);
}

__global__ void __launch_bounds__(256)
transpose_w1_kernel(const float* __restrict__ W1)
{
    __shared__ float tile[32][33];
    int n0 = blockIdx.x * 32;
    int k0 = blockIdx.y * 32;
    int tx = threadIdx.x % 32, ty = threadIdx.x / 32;
#pragma unroll
    for (int j = 0; j < 4; ++j)
        tile[ty + 8*j][tx] = W1[(size_t)(k0 + ty + 8*j) * 512 + n0 + tx];
    __syncthreads();
#pragma unroll
    for (int j = 0; j < 4; ++j) {
        float v = tile[tx][ty + 8*j];
        __nv_bfloat16 h = __float2bfloat16_rn(v);
        __nv_bfloat16 l = __float2bfloat16_rn(v - __bfloat162float(h));
        size_t o = (size_t)(n0 + ty + 8*j) * 2048 + k0 + tx;
        g_wh[o] = h;
        g_wl[o] = l;
    }
}

// ------------------------------------------------------------
// gemm1 via mma.sync bf16 split-3 (proven since R5)
// ------------------------------------------------------------
__global__ void __launch_bounds__(256)
gemm1_mma_kernel(const float* __restrict__ b1)
{
    extern __shared__ __align__(128) char smem[];
    const uint32_t sb = smem_u32(smem);
    const int tid  = threadIdx.x;
    const int wid  = tid >> 5;
    const int lane = tid & 31;
    const int wm = wid & 1, wn = wid >> 1;
    const int bm = blockIdx.y * 128, bn = blockIdx.x * 128;

    float acc[4][4][4];
#pragma unroll
    for (int mt = 0; mt < 4; ++mt)
#pragma unroll
        for (int nt = 0; nt < 4; ++nt)
#pragma unroll
            for (int j = 0; j < 4; ++j) acc[mt][nt][j] = 0.f;

    const __nv_bfloat16* srcs[4] = { g_xh, g_xl, g_wh, g_wl };

    {
#pragma unroll
        for (int t = 0; t < 4; ++t) {
            int row0 = (t < 2) ? bm : bn;
            uint32_t base = sb + t * 16384u;
#pragma unroll
            for (int it = 0; it < 4; ++it) {
                int id = tid + it * 256;
                int r = id >> 3, blk = id & 7;
                cp_async16(base + swz((uint32_t)(r * 128 + blk * 16)),
                           srcs[t] + (size_t)(row0 + r) * 2048 + blk * 8);
            }
        }
        CP_COMMIT();
    }

#pragma unroll 1
    for (int c = 0; c < 32; ++c) {
        if (c + 1 < 32) {
            const int kt = (c + 1) * 64;
            const uint32_t bufo = (uint32_t)((c + 1) & 1) * 65536u;
#pragma unroll
            for (int t = 0; t < 4; ++t) {
                int row0 = (t < 2) ? bm : bn;
                uint32_t base = sb + bufo + t * 16384u;
#pragma unroll
                for (int it = 0; it < 4; ++it) {
                    int id = tid + it * 256;
                    int r = id >> 3, blk = id & 7;
                    cp_async16(base + swz((uint32_t)(r * 128 + blk * 16)),
                               srcs[t] + (size_t)(row0 + r) * 2048 + kt + blk * 8);
                }
            }
            CP_COMMIT();
            CP_WAIT(1);
        } else {
            CP_WAIT(0);
        }
        __syncthreads();

        const uint32_t base = sb + (uint32_t)(c & 1) * 65536u;
#pragma unroll
        for (int kk = 0; kk < 4; ++kk) {
            uint32_t ah[4][4], al[4][4], bh[4][2], bl[4][2];
#pragma unroll
            for (int mt = 0; mt < 4; ++mt) {
                uint32_t byte = (uint32_t)((wm * 64 + mt * 16 + (lane & 15)) * 128
                                           + (kk * 2 + (lane >> 4)) * 16);
                uint32_t ad = base + swz(byte);
                ldm_x4(ah[mt], ad);
                ldm_x4(al[mt], ad + 16384u);
            }
#pragma unroll
            for (int nt = 0; nt < 4; ++nt) {
                uint32_t byte = (uint32_t)((wn * 32 + nt * 8 + (lane & 7)) * 128
                                           + (kk * 2 + ((lane >> 3) & 1)) * 16);
                uint32_t bd = base + 32768u + swz(byte);
                ldm_x2(bh[nt], bd);
                ldm_x2(bl[nt], bd + 16384u);
            }
#pragma unroll
            for (int mt = 0; mt < 4; ++mt)
#pragma unroll
                for (int nt = 0; nt < 4; ++nt) {
                    mma_bf16(acc[mt][nt], ah[mt], bh[nt]);
                    mma_bf16(acc[mt][nt], ah[mt], bl[nt]);
                    mma_bf16(acc[mt][nt], al[mt], bh[nt]);
                }
        }
        __syncthreads();
    }

#pragma unroll
    for (int mt = 0; mt < 4; ++mt) {
        int row = bm + wm * 64 + mt * 16 + (lane >> 2);
#pragma unroll
        for (int nt = 0; nt < 4; ++nt) {
            int col = bn + wn * 32 + nt * 8 + (lane & 3) * 2;
            float b0 = b1[col], bq = b1[col + 1];
            float2 v0 = make_float2(fmaxf(acc[mt][nt][0] + b0, 0.f),
                                    fmaxf(acc[mt][nt][1] + bq, 0.f));
            float2 v1 = make_float2(fmaxf(acc[mt][nt][2] + b0, 0.f),
                                    fmaxf(acc[mt][nt][3] + bq, 0.f));
            *reinterpret_cast<float2*>(&g_H[(size_t)row * 512 + col])       = v0;
            *reinterpret_cast<float2*>(&g_H[(size_t)(row + 8) * 512 + col]) = v1;
        }
    }
}

// ------------------------------------------------------------
// fp32 SGEMM for gemm2 — 32x64 tiles, split-K=4 => 1024 CTAs
// ------------------------------------------------------------
template<int BM, int BN, int BK, int TM, int TN>
__device__ __forceinline__ void sgemm_body(
    const float* __restrict__ A, const float* __restrict__ Bm,
    const float* __restrict__ bias, float* __restrict__ C,
    int N, int K, int lda)
{
    __shared__ float As[BK][BM];
    __shared__ float Bs[BK][BN];
    const int tid = threadIdx.x;
    const int NX = BN / TN;
    const int tx = tid % NX;
    const int ty = tid / NX;
    const int bm = blockIdx.y * BM;
    const int bn = blockIdx.x * BN;

    ull acc[TM / 2][TN];
#pragma unroll
    for (int i = 0; i < TM / 2; ++i)
#pragma unroll
        for (int j = 0; j < TN; ++j) acc[i][j] = 0ull;

    for (int kt = 0; kt < K; kt += BK) {
#pragma unroll
        for (int l = 0; l < (BM * BK) / (256 * 4); ++l) {
            int id  = tid + l * 256;
            int row = id / (BK / 4);
            int c   = id % (BK / 4);
            float4 v = *reinterpret_cast<const float4*>(
                A + (size_t)(bm + row) * lda + kt + c * 4);
            As[c*4+0][row] = v.x; As[c*4+1][row] = v.y;
            As[c*4+2][row] = v.z; As[c*4+3][row] = v.w;
        }
#pragma unroll
        for (int l = 0; l < (BK * BN) / (256 * 4); ++l) {
            int id = tid + l * 256;
            int kr = id / (BN / 4);
            int c  = id % (BN / 4);
            *reinterpret_cast<float4*>(&Bs[kr][c*4]) =
                *reinterpret_cast<const float4*>(
                    Bm + (size_t)(kt + kr) * N + bn + c * 4);
        }
        __syncthreads();
#pragma unroll
        for (int k = 0; k < BK; ++k) {
            ull ra[TM / 2];
            float rb[TN];
#pragma unroll
            for (int i = 0; i < TM / 2; ++i)
                ra[i] = *reinterpret_cast<const ull*>(&As[k][ty*TM + 2*i]);
#pragma unroll
            for (int j = 0; j < TN; j += 4)
                *reinterpret_cast<float4*>(&rb[j]) =
                    *reinterpret_cast<const float4*>(&Bs[k][tx*TN + j]);
#pragma unroll
            for (int j = 0; j < TN; ++j) {
                ull rbb = pack2(rb[j], rb[j]);
#pragma unroll
                for (int i = 0; i < TM / 2; ++i)
                    acc[i][j] = f2fma(ra[i], rbb, acc[i][j]);
            }
        }
        __syncthreads();
    }
#pragma unroll
    for (int i = 0; i < TM / 2; ++i) {
        int row = bm + ty * TM + 2 * i;
#pragma unroll
        for (int j = 0; j < TN; ++j) {
            int col = bn + tx * TN + j;
            float bv = bias ? bias[col] : 0.f;
            float2 u = unpack2(acc[i][j]);
            C[(size_t)row * N + col]       = u.x + bv;
            C[(size_t)(row + 1) * N + col] = u.y + bv;
        }
    }
}

__global__ void __launch_bounds__(256)
gemm2_kernel(const float* __restrict__ W2, const float* __restrict__ b2)
{
    const int z = blockIdx.z;
    const float* A  = g_H + z * 128;
    const float* Bm = W2 + (size_t)(z * 128) * 128;
    float* C = g_comp[z];
    sgemm_body<32, 64, 32, 2, 4>(A, Bm, z ? nullptr : b2, C, 128, 128, 512);
}

// ------------------------------------------------------------
// amp kernel: A[b, 2j|2j+1] = cos/sin(com_j/2) * 2^-3.5, bf16 split
// ------------------------------------------------------------
__global__ void __launch_bounds__(256)
amp_kernel()
{
    int id = blockIdx.x * 256 + threadIdx.x;
    int b = id >> 7, j = id & 127;
    const float inv = 0.08838834764831844f;    // 2^-3.5
    float a = 0.5f * (g_comp[0][b * 128 + j] + g_comp[1][b * 128 + j]
                    + g_comp[2][b * 128 + j] + g_comp[3][b * 128 + j]);
    float sa, ca; sincosf(a, &sa, &ca);
    float vc = ca * inv, vs = sa * inv;
    __nv_bfloat16 ch = __float2bfloat16_rn(vc);
    __nv_bfloat16 cl = __float2bfloat16_rn(vc - __bfloat162float(ch));
    __nv_bfloat16 sh = __float2bfloat16_rn(vs);
    __nv_bfloat16 sl = __float2bfloat16_rn(vs - __bfloat162float(sh));
    size_t o = (size_t)b * 256 + 2 * j;
    g_ah[o] = ch; g_ah[o + 1] = sh;
    g_al[o] = cl; g_al[o + 1] = sl;
}

// ------------------------------------------------------------
// U-build (proven at R9): evolve 256 basis columns, emit bf16
// hi/lo of re/im at permuted position (pairs adjacent).
// ------------------------------------------------------------
struct GroupMeta {
    unsigned cmk[4];
    unsigned rmk[4];
    unsigned d[8];
    int      gidx[4];
};
struct CircMeta {
    GroupMeta grp[12];
    unsigned lfmask[11];
    unsigned cz;
    unsigned minv[12];
};

__global__ void __launch_bounds__(256, 3)
ubuild_kernel(const float* __restrict__ asz, CircMeta meta)
{
    __shared__ float2 st[4096];
    __shared__ ull    mats[48][8];
    const int c   = blockIdx.x;
    const int tid = threadIdx.x;
    ull* stq = reinterpret_cast<ull*>(st);

    if (tid < 48) {
        float phi = asz[tid*3+0], th = asz[tid*3+1], om = asz[tid*3+2];
        float cc, s, cp, sp, cm, sm;
        sincosf(0.5f * th, &s, &cc);
        sincosf(0.5f * (phi + om), &sp, &cp);
        sincosf(0.5f * (phi - om), &sm, &cm);
        float2 m00 = make_float2( cp * cc, -sp * cc);
        float2 m01 = make_float2(-cm * s,  -sm * s);
        float2 m10 = make_float2( cm * s,  -sm * s);
        float2 m11 = make_float2( cp * cc,  sp * cc);
        mats[tid][0] = pack2(m00.x, m00.x); mats[tid][1] = pack2(-m00.y, m00.y);
        mats[tid][2] = pack2(m01.x, m01.x); mats[tid][3] = pack2(-m01.y, m01.y);
        mats[tid][4] = pack2(m10.x, m10.x); mats[tid][5] = pack2(-m10.y, m10.y);
        mats[tid][6] = pack2(m11.x, m11.x); mats[tid][7] = pack2(-m11.y, m11.y);
    }
#pragma unroll
    for (int i = 0; i < 16; ++i) st[tid + i * 256] = make_float2(0.f, 0.f);
    __syncthreads();

    if (tid == 0) {
        int j = c >> 1, t = c & 1;
        int rj = (int)(__brev((unsigned)j) >> 25);  // rev7
        int n0 = (t ? 2048 : 0) + rj * 16;
        st[n0] = make_float2(1.f, 0.f);
    }
    __syncthreads();

#pragma unroll 1
    for (int G = 0; G < 12; ++G) {
        const GroupMeta& gm = meta.grp[G];
        unsigned rep = 0;
#pragma unroll
        for (int j = 0; j < 8; ++j)
            rep ^= ((tid >> j) & 1u) ? gm.d[j] : 0u;

        unsigned idx[16];
#pragma unroll
        for (int bb = 0; bb < 16; ++bb) {
            unsigned o = rep;
            if (bb & 1) o ^= gm.cmk[0];
            if (bb & 2) o ^= gm.cmk[1];
            if (bb & 4) o ^= gm.cmk[2];
            if (bb & 8) o ^= gm.cmk[3];
            idx[bb] = o;
        }
        ull v[16];
#pragma unroll
        for (int bb = 0; bb < 16; ++bb) v[bb] = stq[idx[bb]];

#pragma unroll
        for (int gg = 0; gg < 4; ++gg) {
            const ull* mp = mats[gm.gidx[gg]];
            bool lb = (__popc(gm.rmk[gg] & rep) & 1) != 0;
            ull a0r = lb ? mp[6] : mp[0], a0i = lb ? mp[7] : mp[1];
            ull a1r = lb ? mp[4] : mp[2], a1i = lb ? mp[5] : mp[3];
            ull b0r = lb ? mp[2] : mp[4], b0i = lb ? mp[3] : mp[5];
            ull b1r = lb ? mp[0] : mp[6], b1i = lb ? mp[1] : mp[7];
            const unsigned bit = 1u << gg;
#pragma unroll
            for (int bb = 0; bb < 16; ++bb) {
                if (bb & bit) continue;
                ull s0 = v[bb], s1 = v[bb ^ bit];
                ull s0s = uswap(s0), s1s = uswap(s1);
                ull n0 = f2mul(a0r, s0);
                n0 = f2fma(a0i, s0s, n0);
                n0 = f2fma(a1r, s1, n0);
                n0 = f2fma(a1i, s1s, n0);
                ull n1 = f2mul(b0r, s0);
                n1 = f2fma(b0i, s0s, n1);
                n1 = f2fma(b1r, s1, n1);
                n1 = f2fma(b1i, s1s, n1);
                v[bb] = n0; v[bb ^ bit] = n1;
            }
        }
#pragma unroll
        for (int bb = 0; bb < 16; ++bb) stq[idx[bb]] = v[bb];
        __syncthreads();
    }

#pragma unroll
    for (int i = 0; i < 16; ++i) {
        unsigned n = tid + i * 256;
        unsigned iw = 0;
#pragma unroll
        for (int q = 0; q < 12; ++q)
            iw |= (unsigned)(__popc(meta.minv[q] & n) & 1) << q;
        unsigned p = ((iw & 2047u) << 1) | (iw >> 11);
        float2 s = st[n];
        __nv_bfloat16 rh = __float2bfloat16_rn(s.x);
        __nv_bfloat16 rl = __float2bfloat16_rn(s.x - __bfloat162float(rh));
        __nv_bfloat16 ih = __float2bfloat16_rn(s.y);
        __nv_bfloat16 il = __float2bfloat16_rn(s.y - __bfloat162float(ih));
        size_t o = (size_t)c * 4096 + p;
        g_utmp[0][o] = rh; g_utmp[1][o] = rl;
        g_utmp[2][o] = ih; g_utmp[3][o] = il;
    }
}

// transpose U staging [c][p] -> k-contig [p][c]
__global__ void __launch_bounds__(256)
transpose_u_kernel()
{
    __shared__ __nv_bfloat16 t[32][33];
    const int z  = blockIdx.z;
    const int p0 = blockIdx.x * 32;
    const int c0 = blockIdx.y * 32;
    int tx = threadIdx.x % 32, ty = threadIdx.x / 32;
#pragma unroll
    for (int j = 0; j < 4; ++j)
        t[ty + 8*j][tx] = g_utmp[z][(size_t)(c0 + ty + 8*j) * 4096 + p0 + tx];
    __syncthreads();
#pragma unroll
    for (int j = 0; j < 4; ++j)
        g_u[z][(size_t)(p0 + ty + 8*j) * 256 + c0 + tx] = t[tx][ty + 8*j];
}

// ------------------------------------------------------------
// Fused state GEMM + measurement — R11 double-buffered version
// (proven 334us path; 163840 B dynamic smem, x staged in smem).
// CTA tile 64(M=batch) x 128(N=state pairs), K=256.
// ------------------------------------------------------------
__global__ void __launch_bounds__(256)
state_fused_kernel(const float* __restrict__ x)
{
    extern __shared__ __align__(128) char smem[];
    __shared__ float psum[64][4];
    __shared__ float xs[64][68];          // stride 68: conflict-free epilogue
    const uint32_t sb = smem_u32(smem);
    const int tid = threadIdx.x;
    const int wid = tid >> 5, lane = tid & 31;
    const int wm = wid & 1, wn = wid >> 1;
    const int bm = blockIdx.y * 64;
    const int bx = blockIdx.x;            // N tile (128 cols = 64 pairs)
    const int bn = bx * 128;

    float accre[2][4][4], accim[2][4][4];
#pragma unroll
    for (int mt = 0; mt < 2; ++mt)
#pragma unroll
        for (int nt = 0; nt < 4; ++nt)
#pragma unroll
            for (int j = 0; j < 4; ++j) { accre[mt][nt][j] = 0.f; accim[mt][nt][j] = 0.f; }

    const __nv_bfloat16* bsrc[4] = { g_u[0], g_u[1], g_u[2], g_u[3] };

    // prologue chunk 0
    {
#pragma unroll
        for (int s = 0; s < 2; ++s) {
            const __nv_bfloat16* g = s ? g_al : g_ah;
#pragma unroll
            for (int it = 0; it < 2; ++it) {
                int id = tid + it * 256;
                int r = id >> 3, blk = id & 7;
                cp_async16(sb + (uint32_t)(s * 8192) + swz((uint32_t)(r * 128 + blk * 16)),
                           g + (size_t)(bm + r) * 256 + blk * 8);
            }
        }
#pragma unroll
        for (int z = 0; z < 4; ++z) {
#pragma unroll
            for (int it = 0; it < 4; ++it) {
                int id = tid + it * 256;
                int r = id >> 3, blk = id & 7;
                cp_async16(sb + 16384u + (uint32_t)(z * 16384) + swz((uint32_t)(r * 128 + blk * 16)),
                           bsrc[z] + (size_t)(bn + r) * 256 + blk * 8);
            }
        }
        CP_COMMIT();
    }

    // stage x tile [64 rows][64 cols] coalesced (overlaps with TC pipeline)
#pragma unroll
    for (int it = 0; it < 4; ++it) {
        int id = tid + it * 256;          // 1024 float4 loads = 64 x 16
        int r = id >> 4, c4 = id & 15;
        float4 v = *reinterpret_cast<const float4*>(
            &x[(size_t)(bm + r) * 2048 + bx * 64 + c4 * 4]);
        xs[r][c4 * 4 + 0] = v.x;
        xs[r][c4 * 4 + 1] = v.y;
        xs[r][c4 * 4 + 2] = v.z;
        xs[r][c4 * 4 + 3] = v.w;
    }

#pragma unroll 1
    for (int c = 0; c < 4; ++c) {
        if (c + 1 < 4) {
            const int kt = (c + 1) * 64;
            const uint32_t bufo = (uint32_t)((c + 1) & 1) * 81920u;
#pragma unroll
            for (int s = 0; s < 2; ++s) {
                const __nv_bfloat16* g = s ? g_al : g_ah;
#pragma unroll
                for (int it = 0; it < 2; ++it) {
                    int id = tid + it * 256;
                    int r = id >> 3, blk = id & 7;
                    cp_async16(sb + bufo + (uint32_t)(s * 8192) + swz((uint32_t)(r * 128 + blk * 16)),
                               g + (size_t)(bm + r) * 256 + kt + blk * 8);
                }
            }
#pragma unroll
            for (int z = 0; z < 4; ++z) {
#pragma unroll
                for (int it = 0; it < 4; ++it) {
                    int id = tid + it * 256;
                    int r = id >> 3, blk = id & 7;
                    cp_async16(sb + bufo + 16384u + (uint32_t)(z * 16384) + swz((uint32_t)(r * 128 + blk * 16)),
                               bsrc[z] + (size_t)(bn + r) * 256 + kt + blk * 8);
                }
            }
            CP_COMMIT();
            CP_WAIT(1);
        } else {
            CP_WAIT(0);
        }
        __syncthreads();

        const uint32_t base = sb + (uint32_t)(c & 1) * 81920u;
#pragma unroll
        for (int kk = 0; kk < 4; ++kk) {
            uint32_t ah[2][4], al[2][4];
#pragma unroll
            for (int mt = 0; mt < 2; ++mt) {
                uint32_t byte = (uint32_t)((wm * 32 + mt * 16 + (lane & 15)) * 128
                                           + (kk * 2 + (lane >> 4)) * 16);
                uint32_t ad = base + swz(byte);
                ldm_x4(ah[mt], ad);
                ldm_x4(al[mt], ad + 8192u);
            }
#pragma unroll
            for (int nt = 0; nt < 4; ++nt) {
                uint32_t byte = (uint32_t)((wn * 32 + nt * 8 + (lane & 7)) * 128
                                           + (kk * 2 + ((lane >> 3) & 1)) * 16);
                uint32_t sw = swz(byte);
                uint32_t brh[2], brl[2], bih[2], bil[2];
                ldm_x2(brh, base + 16384u + sw);
                ldm_x2(brl, base + 32768u + sw);
                ldm_x2(bih, base + 49152u + sw);
                ldm_x2(bil, base + 65536u + sw);
#pragma unroll
                for (int mt = 0; mt < 2; ++mt) {
                    mma_bf16(accre[mt][nt], ah[mt], brh);
                    mma_bf16(accre[mt][nt], ah[mt], brl);
                    mma_bf16(accre[mt][nt], al[mt], brh);
                    mma_bf16(accim[mt][nt], ah[mt], bih);
                    mma_bf16(accim[mt][nt], ah[mt], bil);
                    mma_bf16(accim[mt][nt], al[mt], bih);
                }
            }
        }
        __syncthreads();
    }

    // fused measurement epilogue: x from smem (conflict-free)
    float rowacc[2][2];
    rowacc[0][0] = rowacc[0][1] = rowacc[1][0] = rowacc[1][1] = 0.f;
#pragma unroll
    for (int mt = 0; mt < 2; ++mt) {
#pragma unroll
        for (int nt = 0; nt < 4; ++nt) {
            int lj = wn * 16 + nt * 4 + (lane & 3);
            int lr0 = wm * 32 + mt * 16 + (lane >> 2);
#pragma unroll
            for (int off = 0; off < 2; ++off) {
                float s0r = accre[mt][nt][off * 2];
                float s1r = accre[mt][nt][off * 2 + 1];
                float s0i = accim[mt][nt][off * 2];
                float s1i = accim[mt][nt][off * 2 + 1];
                float xv = xs[lr0 + off * 8][lj];
                float sv, cv;
                sincosf(xv, &sv, &cv);
                rowacc[mt][off] += cv * ((s1r*s1r + s1i*s1i) - (s0r*s0r + s0i*s0i))
                                 - 2.f * sv * (s0r*s1r + s0i*s1i);
            }
        }
    }
#pragma unroll
    for (int mt = 0; mt < 2; ++mt)
#pragma unroll
        for (int off = 0; off < 2; ++off) {
            float r = rowacc[mt][off];
            r += __shfl_down_sync(0xffffffffu, r, 2);
            r += __shfl_down_sync(0xffffffffu, r, 1);
            if ((lane & 3) == 0)
                psum[wm * 32 + mt * 16 + (lane >> 2) + off * 8][wn] = r;
        }
    __syncthreads();
    if (tid < 64)
        g_part[bx][bm + tid] =
            psum[tid][0] + psum[tid][1] + psum[tid][2] + psum[tid][3];
}

__global__ void __launch_bounds__(256)
finalsum_kernel(float* __restrict__ out)
{
    int b = blockIdx.x * 256 + threadIdx.x;
    float s = 0.f;
#pragma unroll
    for (int z = 0; z < 32; ++z) s += g_part[z][b];
    out[b] = s;
}

// ------------------------------------------------------------
// Host: GF(2) bookkeeping (proven) + minv
// ------------------------------------------------------------
struct Ech {
    unsigned e[12];
    Ech() { for (int i = 0; i < 12; ++i) e[i] = 0; }
    unsigned reduce(unsigned v) const {
        for (int b = 11; b >= 0; --b)
            if (((v >> b) & 1u) && e[b]) v ^= e[b];
        return v;
    }
    bool insert(unsigned v) {
        v = reduce(v);
        if (!v) return false;
        int b = 11;
        while (!((v >> b) & 1u)) --b;
        e[b] = v;
        return true;
    }
};

static unsigned gf2_cnot_rev(unsigned v, int r) {
    for (int w = 11; w >= 0; --w) {
        int t = (w + r) % 12;
        if ((v >> (11 - w)) & 1u) v ^= 1u << (11 - t);
    }
    return v;
}

static void gf2_invert(const unsigned colv[12], unsigned invr[12]) {
    unsigned row[12], aug[12];
    for (int p = 0; p < 12; ++p) {
        unsigned rr = 0;
        for (int q = 0; q < 12; ++q) rr |= ((colv[q] >> p) & 1u) << q;
        row[p] = rr; aug[p] = 1u << p;
    }
    for (int i = 0; i < 12; ++i) {
        int piv = i;
        while (!((row[piv] >> i) & 1u)) ++piv;
        unsigned t = row[i]; row[i] = row[piv]; row[piv] = t;
        t = aug[i]; aug[i] = aug[piv]; aug[piv] = t;
        for (int jj = 0; jj < 12; ++jj)
            if (jj != i && ((row[jj] >> i) & 1u)) {
                row[jj] ^= row[i]; aug[jj] ^= aug[i];
            }
    }
    for (int p = 0; p < 12; ++p) invr[p] = aug[p];
}

static void build_meta(CircMeta& meta) {
    unsigned macc[12];
    for (int p = 0; p < 12; ++p) macc[p] = 1u << p;
    for (int l = 0; l < 4; ++l) {
        unsigned row[12], aug[12];
        for (int p = 0; p < 12; ++p) {
            unsigned rr = 0;
            for (int q = 0; q < 12; ++q) rr |= ((macc[q] >> p) & 1u) << q;
            row[p] = rr; aug[p] = 1u << p;
        }
        for (int i = 0; i < 12; ++i) {
            int piv = i;
            while (!((row[piv] >> i) & 1u)) ++piv;
            unsigned t = row[i]; row[i] = row[piv]; row[piv] = t;
            t = aug[i]; aug[i] = aug[piv]; aug[piv] = t;
            for (int jj = 0; jj < 12; ++jj)
                if (jj != i && ((row[jj] >> i) & 1u)) {
                    row[jj] ^= row[i]; aug[jj] ^= aug[i];
                }
        }
        for (int grp = 0; grp < 3; ++grp) {
            GroupMeta& gm = meta.grp[l * 3 + grp];
            Ech ech;
            for (int t = 0; t < 4; ++t) {
                int w = grp * 4 + t;
                gm.cmk[t]  = macc[11 - w];
                gm.rmk[t]  = aug[11 - w];
                gm.gidx[t] = l * 12 + w;
                ech.insert(gm.cmk[t]);
            }
            int nd = 0;
            unsigned proje[5] = {0, 0, 0, 0, 0};
            for (unsigned v = 1; v < 4096 && nd < 5; ++v) {
                if (ech.reduce(v) == 0) continue;
                unsigned p = v & 31u;
                for (int b = 4; b >= 0; --b)
                    if (((p >> b) & 1u) && proje[b]) p ^= proje[b];
                if (p == 0) continue;
                ech.insert(v);
                int pb = 4;
                while (!((p >> pb) & 1u)) --pb;
                proje[pb] = p;
                gm.d[nd++] = v;
            }
            for (unsigned v = 1; v < 4096 && nd < 8; ++v)
                if (ech.insert(v)) gm.d[nd++] = v;
        }
        int r = l % 11 + 1;
        unsigned nmacc[12];
        for (int p = 0; p < 12; ++p) {
            unsigned u = gf2_cnot_rev(1u << p, r);
            unsigned a = 0;
            for (int q = 0; q < 12; ++q)
                if ((u >> q) & 1u) a ^= macc[q];
            nmacc[p] = a;
        }
        for (int p = 0; p < 12; ++p) macc[p] = nmacc[p];
    }
    for (int q = 0; q < 11; ++q) meta.lfmask[q] = macc[10 - q];
    meta.cz = macc[11];

    unsigned colv[12];
    for (int q = 0; q < 11; ++q) colv[q] = meta.lfmask[q];
    colv[11] = meta.cz;
    gf2_invert(colv, meta.minv);
}

// ------------------------------------------------------------
// Side stream for the U-build chain (created once at load time,
// before any capture; fork/join via events is capture-legal).
// ------------------------------------------------------------
struct StreamPack {
    cudaStream_t s2;
    cudaEvent_t evF, evJ;
    StreamPack() {
        cudaStreamCreateWithFlags(&s2, cudaStreamNonBlocking);
        cudaEventCreateWithFlags(&evF, cudaEventDisableTiming);
        cudaEventCreateWithFlags(&evJ, cudaEventDisableTiming);
    }
};
static StreamPack g_sp;

// ------------------------------------------------------------
extern "C" void kernel_launch(void* const* d_in, const int* in_sizes, int n_in,
                              void* d_out, int out_size)
{
    const float* x   = (const float*)d_in[0];
    const float* W1  = (const float*)d_in[1];
    const float* b1  = (const float*)d_in[2];
    const float* W2  = (const float*)d_in[3];
    const float* b2  = (const float*)d_in[4];
    const float* asz = (const float*)d_in[5];
    float* out = (float*)d_out;

    CircMeta meta;
    build_meta(meta);

    cudaFuncSetAttribute(gemm1_mma_kernel,
                         cudaFuncAttributeMaxDynamicSharedMemorySize, 131072);
    cudaFuncSetAttribute(state_fused_kernel,
                         cudaFuncAttributeMaxDynamicSharedMemorySize, 163840);

    // fork: U-build chain on side stream (independent of classical path)
    cudaEventRecord(g_sp.evF, 0);
    cudaStreamWaitEvent(g_sp.s2, g_sp.evF, 0);
    ubuild_kernel<<<256, 256, 0, g_sp.s2>>>(asz, meta);
    transpose_u_kernel<<<dim3(128, 8, 4), 256, 0, g_sp.s2>>>();
    cudaEventRecord(g_sp.evJ, g_sp.s2);

    // classical path on default stream
    convert_x_kernel<<<4096 * 2048 / 4 / 256, 256>>>(x);
    transpose_w1_kernel<<<dim3(16, 64), 256>>>(W1);
    gemm1_mma_kernel<<<dim3(4, 32), 256, 131072>>>(b1);
    gemm2_kernel<<<dim3(2, 128, 4), 256>>>(W2, b2);
    amp_kernel<<<2048, 256>>>();

    // join, then fused state GEMM + measurement
    cudaStreamWaitEvent(0, g_sp.evJ, 0);
    state_fused_kernel<<<dim3(32, 64), 256, 163840>>>(x);
    finalsum_kernel<<<16, 256>>>(out);
}